// round 2
// baseline (speedup 1.0000x reference)
#include <cuda_runtime.h>

// E=500000, P=4000000, D=U=64.
// Scratch for transformed features (feat @ W): 128 MB __device__ global.
__device__ float g_xform[500000 * 64];

// f32x2 helpers (sm_103a packed fp32 pipe; only reachable via PTX)
#define FMA2(d, a, b) \
    asm("fma.rn.f32x2 %0, %1, %2, %0;" : "+l"(d) : "l"(a), "l"(b))
#define PACK2(p, x) \
    asm("mov.b64 %0, {%1, %1};" : "=l"(p) : "f"(x))
#define UNPACK2(lo, hi, p) \
    asm("mov.b64 {%0, %1}, %2;" : "=f"(lo), "=f"(hi) : "l"(p))

// ---------------------------------------------------------------------------
// Kernel 1: g_xform = feat @ W ; also out[e,:] = bias (scatter then
// accumulates directly into d_out).
// 64x64 tile per block, 256 threads, 4x4 register tile per thread.
// Accumulators packed over ROW pairs as f32x2 so the A operand is a direct
// aligned LDS.64 from the transposed smem tile (pad 66 -> 8B alignment).
// ---------------------------------------------------------------------------
__global__ void __launch_bounds__(256) transform_kernel(
    const float* __restrict__ feat,   // [E, 64]
    const float* __restrict__ W,      // [64, 64]
    const float* __restrict__ bias,   // [64]
    float* __restrict__ out,          // [E, 64]
    int E)
{
    __shared__ float sW[64 * 64];     // sW[k*64 + u]
    __shared__ float sA[64 * 66];     // sA[k*66 + r]  (transposed, pad 66)

    const int tid  = threadIdx.x;
    const int row0 = blockIdx.x * 64;

    #pragma unroll
    for (int i = tid; i < 64 * 64; i += 256)
        sW[i] = W[i];

    #pragma unroll
    for (int i = tid; i < 64 * 64; i += 256) {
        int r = i >> 6;
        int k = i & 63;
        int row = row0 + r;
        sA[k * 66 + r] = (row < E) ? feat[row * 64 + k] : 0.0f;
    }
    __syncthreads();

    const int rt = tid >> 4;   // rows rt*4 .. rt*4+3
    const int ct = tid & 15;   // cols ct*4 .. ct*4+3

    // acc[rp][j]: packed {row rt*4+2rp, row rt*4+2rp+1}, column ct*4+j
    unsigned long long acc[2][4];
    #pragma unroll
    for (int rp = 0; rp < 2; rp++)
        #pragma unroll
        for (int j = 0; j < 4; j++)
            acc[rp][j] = 0ULL;   // packed {0.0f, 0.0f}

    #pragma unroll
    for (int k = 0; k < 64; k++) {
        const unsigned long long a01 =
            *reinterpret_cast<const unsigned long long*>(&sA[k * 66 + rt * 4]);
        const unsigned long long a23 =
            *reinterpret_cast<const unsigned long long*>(&sA[k * 66 + rt * 4 + 2]);
        const float4 w = *reinterpret_cast<const float4*>(&sW[k * 64 + ct * 4]);

        unsigned long long wx, wy, wz, ww;
        PACK2(wx, w.x); PACK2(wy, w.y); PACK2(wz, w.z); PACK2(ww, w.w);

        FMA2(acc[0][0], a01, wx); FMA2(acc[0][1], a01, wy);
        FMA2(acc[0][2], a01, wz); FMA2(acc[0][3], a01, ww);
        FMA2(acc[1][0], a23, wx); FMA2(acc[1][1], a23, wy);
        FMA2(acc[1][2], a23, wz); FMA2(acc[1][3], a23, ww);
    }

    // Unpack to per-row float4s
    float res[4][4];
    #pragma unroll
    for (int rp = 0; rp < 2; rp++)
        #pragma unroll
        for (int j = 0; j < 4; j++) {
            float lo, hi;
            UNPACK2(lo, hi, acc[rp][j]);
            res[rp * 2 + 0][j] = lo;
            res[rp * 2 + 1][j] = hi;
        }

    const float4 b = *reinterpret_cast<const float4*>(&bias[ct * 4]);

    #pragma unroll
    for (int i = 0; i < 4; i++) {
        int row = row0 + rt * 4 + i;
        if (row < E) {
            float4 v;
            v.x = res[i][0]; v.y = res[i][1]; v.z = res[i][2]; v.w = res[i][3];
            *reinterpret_cast<float4*>(&g_xform[row * 64 + ct * 4]) = v;
            *reinterpret_cast<float4*>(&out[row * 64 + ct * 4])     = b;
        }
    }
}

// ---------------------------------------------------------------------------
// Kernel 2: column-tiled scatter. Pass `c0` handles columns [c0, c0+16):
// per-pass L2 working set = 32 MB xform slice + 32 MB out slice = 64 MB,
// which fits in the 126 MB L2 -> atomic RMW lines and gather rows stay
// resident across the whole pass instead of thrashing to HBM.
// One thread per pair: 1 index load (__ldcs, evict-first so the 32 MB index
// stream doesn't pollute the resident slices), 4x float4 gather (64B
// contiguous), 4x red.global.add.v4.f32.
// ---------------------------------------------------------------------------
__global__ void __launch_bounds__(256) scatter_pass_kernel(
    const int2* __restrict__ nbr,    // [P] : {dst, src}
    float* __restrict__ out,         // [E, 64]
    int P, int c0)
{
    const int p = blockIdx.x * 256 + threadIdx.x;
    if (p >= P) return;

    const int2 e = __ldcs(&nbr[p]);  // e.x = dst edge, e.y = src neighbor

    const float4* __restrict__ src =
        reinterpret_cast<const float4*>(&g_xform[e.y * 64 + c0]);
    float* dst = &out[e.x * 64 + c0];

    const float4 v0 = src[0];
    const float4 v1 = src[1];
    const float4 v2 = src[2];
    const float4 v3 = src[3];

    asm volatile("red.global.add.v4.f32 [%0], {%1, %2, %3, %4};"
                 :: "l"(dst + 0), "f"(v0.x), "f"(v0.y), "f"(v0.z), "f"(v0.w) : "memory");
    asm volatile("red.global.add.v4.f32 [%0], {%1, %2, %3, %4};"
                 :: "l"(dst + 4), "f"(v1.x), "f"(v1.y), "f"(v1.z), "f"(v1.w) : "memory");
    asm volatile("red.global.add.v4.f32 [%0], {%1, %2, %3, %4};"
                 :: "l"(dst + 8), "f"(v2.x), "f"(v2.y), "f"(v2.z), "f"(v2.w) : "memory");
    asm volatile("red.global.add.v4.f32 [%0], {%1, %2, %3, %4};"
                 :: "l"(dst + 12), "f"(v3.x), "f"(v3.y), "f"(v3.z), "f"(v3.w) : "memory");
}

// ---------------------------------------------------------------------------
extern "C" void kernel_launch(void* const* d_in, const int* in_sizes, int n_in,
                              void* d_out, int out_size)
{
    const float* feat = (const float*)d_in[0];   // [E, 64] f32
    const int*   nbr  = (const int*)d_in[1];     // [P, 2]  i32
    const float* W    = (const float*)d_in[2];   // [64, 64] f32
    const float* bias = (const float*)d_in[3];   // [64] f32
    float* out = (float*)d_out;                  // [E, 64] f32

    const int E = in_sizes[0] / 64;
    const int P = in_sizes[1] / 2;

    // Step 1: transform + bias-init of out.
    const int blocksA = (E + 63) / 64;
    transform_kernel<<<blocksA, 256>>>(feat, W, bias, out, E);

    // Step 2: four sequential column-slice scatter passes (launches on one
    // stream serialize, giving the temporal L2 partitioning).
    const int blocksS = (P + 255) / 256;
    for (int pass = 0; pass < 4; pass++)
        scatter_pass_kernel<<<blocksS, 256>>>((const int2*)nbr, out, P, pass * 16);
}

// round 3
// speedup vs baseline: 1.9105x; 1.9105x over previous
#include <cuda_runtime.h>

// E=500000, P=4000000, D=U=64.
static const int E_MAX = 500000;
static const int P_MAX = 4000000;

__device__ int g_counts[500032];     // per-dst neighbor count
__device__ int g_offsets[500032];    // exclusive prefix of counts
__device__ int g_cursor[500032];     // scatter cursors (copy of offsets)
__device__ int g_src_sorted[4000000];// src ids grouped by dst
__device__ int g_blockSums[512];
__device__ int g_blockOffs[512];

// f32x2 helpers (sm_103a packed fp32 pipe, PTX-only)
#define FMA2(d, a, b) \
    asm("fma.rn.f32x2 %0, %1, %2, %0;" : "+l"(d) : "l"(a), "l"(b))
#define PACK2(p, x) \
    asm("mov.b64 %0, {%1, %1};" : "=l"(p) : "f"(x))
#define UNPACK2(lo, hi, p) \
    asm("mov.b64 {%0, %1}, %2;" : "=f"(lo), "=f"(hi) : "l"(p))

// ---------------------------------------------------------------------------
// Sort step 0: zero counts
// ---------------------------------------------------------------------------
__global__ void zero_counts_kernel(int E)
{
    int i = blockIdx.x * 256 + threadIdx.x;
    if (i < E) g_counts[i] = 0;
}

// ---------------------------------------------------------------------------
// Sort step 1: histogram of dst ids (RED path: result unused)
// ---------------------------------------------------------------------------
__global__ void hist_kernel(const int2* __restrict__ nbr, int P)
{
    int p = blockIdx.x * 256 + threadIdx.x;
    if (p >= P) return;
    atomicAdd(&g_counts[nbr[p].x], 1);
}

// ---------------------------------------------------------------------------
// Sort step 2a: per-1024-chunk sums
// ---------------------------------------------------------------------------
__global__ void scan_partial_kernel(int E)
{
    __shared__ int s[256];
    const int tid  = threadIdx.x;
    const int base = blockIdx.x * 1024 + tid * 4;
    int t = 0;
    #pragma unroll
    for (int j = 0; j < 4; j++) {
        int idx = base + j;
        if (idx < E) t += g_counts[idx];
    }
    s[tid] = t;
    __syncthreads();
    // tree reduce
    for (int o = 128; o > 0; o >>= 1) {
        if (tid < o) s[tid] += s[tid + o];
        __syncthreads();
    }
    if (tid == 0) g_blockSums[blockIdx.x] = s[0];
}

// ---------------------------------------------------------------------------
// Sort step 2b: exclusive scan of block sums (single block, NB <= 512)
// ---------------------------------------------------------------------------
__global__ void scan_blocksums_kernel(int NB)
{
    __shared__ int s[512];
    const int tid = threadIdx.x;
    int v = (tid < NB) ? g_blockSums[tid] : 0;
    s[tid] = v;
    __syncthreads();
    for (int o = 1; o < 512; o <<= 1) {
        int t = (tid >= o) ? s[tid - o] : 0;
        __syncthreads();
        s[tid] += t;
        __syncthreads();
    }
    if (tid < NB) g_blockOffs[tid] = s[tid] - v;   // exclusive
}

// ---------------------------------------------------------------------------
// Sort step 2c: per-chunk exclusive scan + add block offset; writes offsets
// and cursor.
// ---------------------------------------------------------------------------
__global__ void scan_final_kernel(int E)
{
    __shared__ int s[256];
    const int tid  = threadIdx.x;
    const int base = blockIdx.x * 1024 + tid * 4;

    int c[4];
    int tsum = 0;
    #pragma unroll
    for (int j = 0; j < 4; j++) {
        int idx = base + j;
        c[j] = (idx < E) ? g_counts[idx] : 0;
        tsum += c[j];
    }
    s[tid] = tsum;
    __syncthreads();
    for (int o = 1; o < 256; o <<= 1) {
        int t = (tid >= o) ? s[tid - o] : 0;
        __syncthreads();
        s[tid] += t;
        __syncthreads();
    }
    int run = g_blockOffs[blockIdx.x] + (s[tid] - tsum);   // exclusive base
    #pragma unroll
    for (int j = 0; j < 4; j++) {
        int idx = base + j;
        if (idx < E) {
            g_offsets[idx] = run;
            g_cursor[idx]  = run;
        }
        run += c[j];
    }
}

// ---------------------------------------------------------------------------
// Sort step 3: scatter src ids into dst-grouped order
// ---------------------------------------------------------------------------
__global__ void sort_scatter_kernel(const int2* __restrict__ nbr, int P)
{
    int p = blockIdx.x * 256 + threadIdx.x;
    if (p >= P) return;
    int2 e = nbr[p];                       // x = dst, y = src
    int pos = atomicAdd(&g_cursor[e.x], 1);
    g_src_sorted[pos] = e.y;
}

// ---------------------------------------------------------------------------
// Fused kernel: for each block of 64 dst rows:
//   1) teams of 4 threads register-sum each dst's neighbor feature rows
//      (gather from feat; 128 MB table ~ L2-resident; no atomics anywhere)
//   2) deposit sums transposed into smem A-tile
//   3) 64x64 f32x2 GEMM with W, add bias, write out
// ---------------------------------------------------------------------------
__global__ void __launch_bounds__(256) agg_gemm_kernel(
    const float* __restrict__ feat,   // [E, 64]
    const float* __restrict__ W,      // [64, 64]
    const float* __restrict__ bias,   // [64]
    float* __restrict__ out,          // [E, 64]
    int E)
{
    __shared__ float sW[64 * 64];     // sW[k*64 + u]
    __shared__ float sA[64 * 66];     // sA[k*66 + r] (transposed, pad 66)

    const int tid  = threadIdx.x;
    const int row0 = blockIdx.x * 64;

    #pragma unroll
    for (int i = tid; i < 64 * 64; i += 256)
        sW[i] = W[i];

    // ---- Phase 1: gather + register accumulation -------------------------
    const int team = tid >> 2;        // 0..63 : local dst row
    const int lane = tid & 3;         // 0..3  : 16-column strip
    const int r    = row0 + team;

    float acc[16];
    #pragma unroll
    for (int j = 0; j < 16; j++) acc[j] = 0.0f;

    if (r < E) {
        const int start = g_offsets[r];
        const int cnt   = g_counts[r];
        const int cbase = lane * 16;
        for (int i = 0; i < cnt; i++) {
            const int s = g_src_sorted[start + i];
            const float4* __restrict__ src =
                reinterpret_cast<const float4*>(&feat[s * 64 + cbase]);
            const float4 v0 = src[0];
            const float4 v1 = src[1];
            const float4 v2 = src[2];
            const float4 v3 = src[3];
            acc[0]  += v0.x; acc[1]  += v0.y; acc[2]  += v0.z; acc[3]  += v0.w;
            acc[4]  += v1.x; acc[5]  += v1.y; acc[6]  += v1.z; acc[7]  += v1.w;
            acc[8]  += v2.x; acc[9]  += v2.y; acc[10] += v2.z; acc[11] += v2.w;
            acc[12] += v3.x; acc[13] += v3.y; acc[14] += v3.z; acc[15] += v3.w;
        }
    }

    // Deposit transposed: sA[k][team], k = lane*16 + j
    #pragma unroll
    for (int j = 0; j < 16; j++)
        sA[(lane * 16 + j) * 66 + team] = acc[j];
    __syncthreads();

    // ---- Phase 2: 64x64 GEMM (f32x2), bias, store ------------------------
    const int rt = tid >> 4;   // rows rt*4 .. rt*4+3
    const int ct = tid & 15;   // cols ct*4 .. ct*4+3

    unsigned long long accq[2][4];
    #pragma unroll
    for (int rp = 0; rp < 2; rp++)
        #pragma unroll
        for (int j = 0; j < 4; j++)
            accq[rp][j] = 0ULL;

    #pragma unroll
    for (int k = 0; k < 64; k++) {
        const unsigned long long a01 =
            *reinterpret_cast<const unsigned long long*>(&sA[k * 66 + rt * 4]);
        const unsigned long long a23 =
            *reinterpret_cast<const unsigned long long*>(&sA[k * 66 + rt * 4 + 2]);
        const float4 w = *reinterpret_cast<const float4*>(&sW[k * 64 + ct * 4]);

        unsigned long long wx, wy, wz, ww;
        PACK2(wx, w.x); PACK2(wy, w.y); PACK2(wz, w.z); PACK2(ww, w.w);

        FMA2(accq[0][0], a01, wx); FMA2(accq[0][1], a01, wy);
        FMA2(accq[0][2], a01, wz); FMA2(accq[0][3], a01, ww);
        FMA2(accq[1][0], a23, wx); FMA2(accq[1][1], a23, wy);
        FMA2(accq[1][2], a23, wz); FMA2(accq[1][3], a23, ww);
    }

    float res[4][4];
    #pragma unroll
    for (int rp = 0; rp < 2; rp++)
        #pragma unroll
        for (int j = 0; j < 4; j++) {
            float lo, hi;
            UNPACK2(lo, hi, accq[rp][j]);
            res[rp * 2 + 0][j] = lo;
            res[rp * 2 + 1][j] = hi;
        }

    const float4 b = *reinterpret_cast<const float4*>(&bias[ct * 4]);

    #pragma unroll
    for (int i = 0; i < 4; i++) {
        int row = row0 + rt * 4 + i;
        if (row < E) {
            float4 v;
            v.x = res[i][0] + b.x;
            v.y = res[i][1] + b.y;
            v.z = res[i][2] + b.z;
            v.w = res[i][3] + b.w;
            *reinterpret_cast<float4*>(&out[row * 64 + ct * 4]) = v;
        }
    }
}

// ---------------------------------------------------------------------------
extern "C" void kernel_launch(void* const* d_in, const int* in_sizes, int n_in,
                              void* d_out, int out_size)
{
    const float* feat = (const float*)d_in[0];   // [E, 64] f32
    const int*   nbr  = (const int*)d_in[1];     // [P, 2]  i32
    const float* W    = (const float*)d_in[2];   // [64, 64] f32
    const float* bias = (const float*)d_in[3];   // [64] f32
    float* out = (float*)d_out;                  // [E, 64] f32

    const int E = in_sizes[0] / 64;
    const int P = in_sizes[1] / 2;

    const int blkE  = (E + 255) / 256;
    const int blkP  = (P + 255) / 256;
    const int NB    = (E + 1023) / 1024;         // <= 512

    // Counting sort of pairs by dst
    zero_counts_kernel<<<blkE, 256>>>(E);
    hist_kernel<<<blkP, 256>>>((const int2*)nbr, P);
    scan_partial_kernel<<<NB, 256>>>(E);
    scan_blocksums_kernel<<<1, 512>>>(NB);
    scan_final_kernel<<<NB, 256>>>(E);
    sort_scatter_kernel<<<blkP, 256>>>((const int2*)nbr, P);

    // Fused aggregate + transform + bias
    const int blkA = (E + 63) / 64;
    agg_gemm_kernel<<<blkA, 256>>>(feat, W, bias, out, E);
}

// round 4
// speedup vs baseline: 1.9133x; 1.0015x over previous
#include <cuda_runtime.h>

// E=500000, P=4000000, D=U=64.
__device__ int g_counts[500032];      // per-dst neighbor count
__device__ int g_offsets[500032];     // exclusive prefix of counts
__device__ int g_cursor[500032];      // scatter cursors
__device__ int g_src_sorted[4000000]; // src ids grouped by dst
__device__ int g_blockSums[512];
__device__ int g_blockOffs[512];

// f32x2 helpers (sm_103a packed fp32 pipe, PTX-only)
#define FMA2(d, a, b) \
    asm("fma.rn.f32x2 %0, %1, %2, %0;" : "+l"(d) : "l"(a), "l"(b))
#define PACK2(p, x) \
    asm("mov.b64 %0, {%1, %1};" : "=l"(p) : "f"(x))
#define UNPACK2(lo, hi, p) \
    asm("mov.b64 {%0, %1}, %2;" : "=f"(lo), "=f"(hi) : "l"(p))

// ---------------------------------------------------------------------------
__global__ void zero_counts_kernel(int E)
{
    int i = blockIdx.x * 256 + threadIdx.x;
    if (i < E) g_counts[i] = 0;
}

// Histogram: 2 pairs per thread via int4 (halves index-stream instructions).
__global__ void hist_kernel(const int4* __restrict__ nbr2, int P2, int P)
{
    int q = blockIdx.x * 256 + threadIdx.x;
    if (q >= P2) return;
    int4 e = __ldcs(&nbr2[q]);         // {dst0, src0, dst1, src1}
    atomicAdd(&g_counts[e.x], 1);
    int p1 = q * 2 + 1;
    if (p1 < P) atomicAdd(&g_counts[e.z], 1);
}

// ---------------------------------------------------------------------------
__global__ void scan_partial_kernel(int E)
{
    __shared__ int s[256];
    const int tid  = threadIdx.x;
    const int base = blockIdx.x * 1024 + tid * 4;
    int t = 0;
    #pragma unroll
    for (int j = 0; j < 4; j++) {
        int idx = base + j;
        if (idx < E) t += g_counts[idx];
    }
    s[tid] = t;
    __syncthreads();
    for (int o = 128; o > 0; o >>= 1) {
        if (tid < o) s[tid] += s[tid + o];
        __syncthreads();
    }
    if (tid == 0) g_blockSums[blockIdx.x] = s[0];
}

__global__ void scan_blocksums_kernel(int NB)
{
    __shared__ int s[512];
    const int tid = threadIdx.x;
    int v = (tid < NB) ? g_blockSums[tid] : 0;
    s[tid] = v;
    __syncthreads();
    for (int o = 1; o < 512; o <<= 1) {
        int t = (tid >= o) ? s[tid - o] : 0;
        __syncthreads();
        s[tid] += t;
        __syncthreads();
    }
    if (tid < NB) g_blockOffs[tid] = s[tid] - v;
}

__global__ void scan_final_kernel(int E)
{
    __shared__ int s[256];
    const int tid  = threadIdx.x;
    const int base = blockIdx.x * 1024 + tid * 4;

    int c[4];
    int tsum = 0;
    #pragma unroll
    for (int j = 0; j < 4; j++) {
        int idx = base + j;
        c[j] = (idx < E) ? g_counts[idx] : 0;
        tsum += c[j];
    }
    s[tid] = tsum;
    __syncthreads();
    for (int o = 1; o < 256; o <<= 1) {
        int t = (tid >= o) ? s[tid - o] : 0;
        __syncthreads();
        s[tid] += t;
        __syncthreads();
    }
    int run = g_blockOffs[blockIdx.x] + (s[tid] - tsum);
    #pragma unroll
    for (int j = 0; j < 4; j++) {
        int idx = base + j;
        if (idx < E) {
            g_offsets[idx] = run;
            g_cursor[idx]  = run;
        }
        run += c[j];
    }
}

// Scatter src ids into dst-grouped order: 2 pairs per thread via int4.
__global__ void sort_scatter_kernel(const int4* __restrict__ nbr2, int P2, int P)
{
    int q = blockIdx.x * 256 + threadIdx.x;
    if (q >= P2) return;
    int4 e = __ldcs(&nbr2[q]);
    int pos0 = atomicAdd(&g_cursor[e.x], 1);
    g_src_sorted[pos0] = e.y;
    int p1 = q * 2 + 1;
    if (p1 < P) {
        int pos1 = atomicAdd(&g_cursor[e.z], 1);
        g_src_sorted[pos1] = e.w;
    }
}

// ---------------------------------------------------------------------------
// Fused aggregate + GEMM.
// Phase 1: team of 4 threads per dst row; neighbor loop unrolled by 4 with
// all indices fetched up front -> 16 independent LDG.128 in flight (MLP~16),
// so L2/DRAM latency is hidden and the Poisson count tail stops mattering.
// Phase 2: 64x64 f32x2 GEMM + bias.
// ---------------------------------------------------------------------------
__global__ void __launch_bounds__(256, 4) agg_gemm_kernel(
    const float* __restrict__ feat,   // [E, 64]
    const float* __restrict__ W,      // [64, 64]
    const float* __restrict__ bias,   // [64]
    float* __restrict__ out,          // [E, 64]
    int E)
{
    __shared__ float sW[64 * 64];     // sW[k*64 + u]
    __shared__ float sA[64 * 66];     // sA[k*66 + r] (transposed, pad 66)

    const int tid  = threadIdx.x;
    const int row0 = blockIdx.x * 64;

    #pragma unroll
    for (int i = tid; i < 64 * 64; i += 256)
        sW[i] = W[i];

    // ---- Phase 1: gather + register accumulation -------------------------
    const int team = tid >> 2;        // local dst row
    const int lane = tid & 3;         // 16-col strip
    const int r    = row0 + team;

    float acc[16];
    #pragma unroll
    for (int j = 0; j < 16; j++) acc[j] = 0.0f;

    if (r < E) {
        const int start = g_offsets[r];
        const int cnt   = g_counts[r];
        const float* __restrict__ fb = feat + lane * 16;

        int i = 0;
        for (; i + 4 <= cnt; i += 4) {
            // 4 independent index loads (broadcast within team)
            const int s0 = g_src_sorted[start + i + 0];
            const int s1 = g_src_sorted[start + i + 1];
            const int s2 = g_src_sorted[start + i + 2];
            const int s3 = g_src_sorted[start + i + 3];
            const float4* p0 = reinterpret_cast<const float4*>(fb + (long)s0 * 64);
            const float4* p1 = reinterpret_cast<const float4*>(fb + (long)s1 * 64);
            const float4* p2 = reinterpret_cast<const float4*>(fb + (long)s2 * 64);
            const float4* p3 = reinterpret_cast<const float4*>(fb + (long)s3 * 64);
            // 16 independent LDG.128
            float4 a0 = p0[0], a1 = p0[1], a2 = p0[2], a3 = p0[3];
            float4 b0 = p1[0], b1 = p1[1], b2 = p1[2], b3 = p1[3];
            float4 c0 = p2[0], c1 = p2[1], c2 = p2[2], c3 = p2[3];
            float4 d0 = p3[0], d1 = p3[1], d2 = p3[2], d3 = p3[3];

            acc[0]+=a0.x+b0.x+c0.x+d0.x;  acc[1]+=a0.y+b0.y+c0.y+d0.y;
            acc[2]+=a0.z+b0.z+c0.z+d0.z;  acc[3]+=a0.w+b0.w+c0.w+d0.w;
            acc[4]+=a1.x+b1.x+c1.x+d1.x;  acc[5]+=a1.y+b1.y+c1.y+d1.y;
            acc[6]+=a1.z+b1.z+c1.z+d1.z;  acc[7]+=a1.w+b1.w+c1.w+d1.w;
            acc[8]+=a2.x+b2.x+c2.x+d2.x;  acc[9]+=a2.y+b2.y+c2.y+d2.y;
            acc[10]+=a2.z+b2.z+c2.z+d2.z; acc[11]+=a2.w+b2.w+c2.w+d2.w;
            acc[12]+=a3.x+b3.x+c3.x+d3.x; acc[13]+=a3.y+b3.y+c3.y+d3.y;
            acc[14]+=a3.z+b3.z+c3.z+d3.z; acc[15]+=a3.w+b3.w+c3.w+d3.w;
        }
        for (; i < cnt; i++) {
            const int s = g_src_sorted[start + i];
            const float4* p = reinterpret_cast<const float4*>(fb + (long)s * 64);
            float4 v0 = p[0], v1 = p[1], v2 = p[2], v3 = p[3];
            acc[0]+=v0.x;  acc[1]+=v0.y;  acc[2]+=v0.z;  acc[3]+=v0.w;
            acc[4]+=v1.x;  acc[5]+=v1.y;  acc[6]+=v1.z;  acc[7]+=v1.w;
            acc[8]+=v2.x;  acc[9]+=v2.y;  acc[10]+=v2.z; acc[11]+=v2.w;
            acc[12]+=v3.x; acc[13]+=v3.y; acc[14]+=v3.z; acc[15]+=v3.w;
        }
    }

    #pragma unroll
    for (int j = 0; j < 16; j++)
        sA[(lane * 16 + j) * 66 + team] = acc[j];
    __syncthreads();

    // ---- Phase 2: 64x64 GEMM (f32x2), bias, store ------------------------
    const int rt = tid >> 4;
    const int ct = tid & 15;

    unsigned long long accq[2][4];
    #pragma unroll
    for (int rp = 0; rp < 2; rp++)
        #pragma unroll
        for (int j = 0; j < 4; j++)
            accq[rp][j] = 0ULL;

    #pragma unroll
    for (int k = 0; k < 64; k++) {
        const unsigned long long a01 =
            *reinterpret_cast<const unsigned long long*>(&sA[k * 66 + rt * 4]);
        const unsigned long long a23 =
            *reinterpret_cast<const unsigned long long*>(&sA[k * 66 + rt * 4 + 2]);
        const float4 w = *reinterpret_cast<const float4*>(&sW[k * 64 + ct * 4]);

        unsigned long long wx, wy, wz, ww;
        PACK2(wx, w.x); PACK2(wy, w.y); PACK2(wz, w.z); PACK2(ww, w.w);

        FMA2(accq[0][0], a01, wx); FMA2(accq[0][1], a01, wy);
        FMA2(accq[0][2], a01, wz); FMA2(accq[0][3], a01, ww);
        FMA2(accq[1][0], a23, wx); FMA2(accq[1][1], a23, wy);
        FMA2(accq[1][2], a23, wz); FMA2(accq[1][3], a23, ww);
    }

    float res[4][4];
    #pragma unroll
    for (int rp = 0; rp < 2; rp++)
        #pragma unroll
        for (int j = 0; j < 4; j++) {
            float lo, hi;
            UNPACK2(lo, hi, accq[rp][j]);
            res[rp * 2 + 0][j] = lo;
            res[rp * 2 + 1][j] = hi;
        }

    const float4 b = *reinterpret_cast<const float4*>(&bias[ct * 4]);

    #pragma unroll
    for (int i = 0; i < 4; i++) {
        int row = row0 + rt * 4 + i;
        if (row < E) {
            float4 v;
            v.x = res[i][0] + b.x;
            v.y = res[i][1] + b.y;
            v.z = res[i][2] + b.z;
            v.w = res[i][3] + b.w;
            *reinterpret_cast<float4*>(&out[row * 64 + ct * 4]) = v;
        }
    }
}

// ---------------------------------------------------------------------------
extern "C" void kernel_launch(void* const* d_in, const int* in_sizes, int n_in,
                              void* d_out, int out_size)
{
    const float* feat = (const float*)d_in[0];   // [E, 64] f32
    const int*   nbr  = (const int*)d_in[1];     // [P, 2]  i32
    const float* W    = (const float*)d_in[2];   // [64, 64] f32
    const float* bias = (const float*)d_in[3];   // [64] f32
    float* out = (float*)d_out;                  // [E, 64] f32

    const int E = in_sizes[0] / 64;
    const int P = in_sizes[1] / 2;

    const int blkE = (E + 255) / 256;
    const int P2   = (P + 1) / 2;                // int4 = 2 pairs
    const int blkP2 = (P2 + 255) / 256;
    const int NB   = (E + 1023) / 1024;          // <= 512

    zero_counts_kernel<<<blkE, 256>>>(E);
    hist_kernel<<<blkP2, 256>>>((const int4*)nbr, P2, P);
    scan_partial_kernel<<<NB, 256>>>(E);
    scan_blocksums_kernel<<<1, 512>>>(NB);
    scan_final_kernel<<<NB, 256>>>(E);
    sort_scatter_kernel<<<blkP2, 256>>>((const int4*)nbr, P2, P);

    const int blkA = (E + 63) / 64;
    agg_gemm_kernel<<<blkA, 256>>>(feat, W, bias, out, E);
}

// round 5
// speedup vs baseline: 2.0795x; 1.0869x over previous
#include <cuda_runtime.h>

// E=500000, P=4000000, D=U=64.
__device__ int g_counts[500032];      // per-dst neighbor count
__device__ int g_offsets[500032];     // exclusive prefix of counts
__device__ int g_cursor[500032];      // scatter cursors
__device__ int g_src_sorted[4000000]; // src ids grouped by dst
__device__ int g_blockSums[512];
__device__ int g_blockOffs[512];

// f32x2 helpers (sm_103a packed fp32 pipe, PTX-only)
#define FMA2(d, a, b) \
    asm("fma.rn.f32x2 %0, %1, %2, %0;" : "+l"(d) : "l"(a), "l"(b))
#define PACK2(p, x) \
    asm("mov.b64 %0, {%1, %1};" : "=l"(p) : "f"(x))
#define UNPACK2(lo, hi, p) \
    asm("mov.b64 {%0, %1}, %2;" : "=f"(lo), "=f"(hi) : "l"(p))

// ---------------------------------------------------------------------------
__global__ void zero_counts_kernel(int E)
{
    int i = blockIdx.x * 256 + threadIdx.x;
    if (i < E) g_counts[i] = 0;
}

__global__ void hist_kernel(const int4* __restrict__ nbr2, int P2, int P)
{
    int q = blockIdx.x * 256 + threadIdx.x;
    if (q >= P2) return;
    int4 e = __ldcs(&nbr2[q]);         // {dst0, src0, dst1, src1}
    atomicAdd(&g_counts[e.x], 1);
    int p1 = q * 2 + 1;
    if (p1 < P) atomicAdd(&g_counts[e.z], 1);
}

__global__ void scan_partial_kernel(int E)
{
    __shared__ int s[256];
    const int tid  = threadIdx.x;
    const int base = blockIdx.x * 1024 + tid * 4;
    int t = 0;
    #pragma unroll
    for (int j = 0; j < 4; j++) {
        int idx = base + j;
        if (idx < E) t += g_counts[idx];
    }
    s[tid] = t;
    __syncthreads();
    for (int o = 128; o > 0; o >>= 1) {
        if (tid < o) s[tid] += s[tid + o];
        __syncthreads();
    }
    if (tid == 0) g_blockSums[blockIdx.x] = s[0];
}

__global__ void scan_blocksums_kernel(int NB)
{
    __shared__ int s[512];
    const int tid = threadIdx.x;
    int v = (tid < NB) ? g_blockSums[tid] : 0;
    s[tid] = v;
    __syncthreads();
    for (int o = 1; o < 512; o <<= 1) {
        int t = (tid >= o) ? s[tid - o] : 0;
        __syncthreads();
        s[tid] += t;
        __syncthreads();
    }
    if (tid < NB) g_blockOffs[tid] = s[tid] - v;
}

__global__ void scan_final_kernel(int E)
{
    __shared__ int s[256];
    const int tid  = threadIdx.x;
    const int base = blockIdx.x * 1024 + tid * 4;

    int c[4];
    int tsum = 0;
    #pragma unroll
    for (int j = 0; j < 4; j++) {
        int idx = base + j;
        c[j] = (idx < E) ? g_counts[idx] : 0;
        tsum += c[j];
    }
    s[tid] = tsum;
    __syncthreads();
    for (int o = 1; o < 256; o <<= 1) {
        int t = (tid >= o) ? s[tid - o] : 0;
        __syncthreads();
        s[tid] += t;
        __syncthreads();
    }
    int run = g_blockOffs[blockIdx.x] + (s[tid] - tsum);
    #pragma unroll
    for (int j = 0; j < 4; j++) {
        int idx = base + j;
        if (idx < E) {
            g_offsets[idx] = run;
            g_cursor[idx]  = run;
        }
        run += c[j];
    }
}

__global__ void sort_scatter_kernel(const int4* __restrict__ nbr2, int P2, int P)
{
    int q = blockIdx.x * 256 + threadIdx.x;
    if (q >= P2) return;
    int4 e = __ldcs(&nbr2[q]);
    int pos0 = atomicAdd(&g_cursor[e.x], 1);
    g_src_sorted[pos0] = e.y;
    int p1 = q * 2 + 1;
    if (p1 < P) {
        int pos1 = atomicAdd(&g_cursor[e.z], 1);
        g_src_sorted[pos1] = e.w;
    }
}

// ---------------------------------------------------------------------------
// Fused aggregate + GEMM.
// Phase 1: HALF-WARP (16-lane) team per dst row, each lane owns one 16B
// column segment -> 1 LDG.128 per lane per neighbor. Neighbor loop unrolled
// by 8 with indices prefetched -> 8 independent LDG.128 in flight per thread
// at only ~4 accumulator regs per row. 4 sequential row-passes per thread
// (also flattens the Poisson straggler: per-thread work ~ Poisson(32)).
// Phase 2: 64x64 f32x2 GEMM + bias.
// ---------------------------------------------------------------------------
__global__ void __launch_bounds__(256) agg_gemm_kernel(
    const float* __restrict__ feat,   // [E, 64]
    const float* __restrict__ W,      // [64, 64]
    const float* __restrict__ bias,   // [64]
    float* __restrict__ out,          // [E, 64]
    int E)
{
    __shared__ float sW[64 * 64];     // sW[k*64 + u]
    __shared__ float sA[64 * 66];     // sA[k*66 + r] (transposed, pad 66)

    const int tid  = threadIdx.x;
    const int row0 = blockIdx.x * 64;

    #pragma unroll
    for (int i = tid; i < 64 * 64; i += 256)
        sW[i] = W[i];

    // ---- Phase 1: gather + register accumulation -------------------------
    const int lane16 = tid & 15;          // column segment (16B)
    const int tteam  = tid >> 4;          // 0..15
    const float* __restrict__ fb = feat + lane16 * 4;

    #pragma unroll
    for (int rr = 0; rr < 4; rr++) {
        const int lr = rr * 16 + tteam;   // local row 0..63
        const int r  = row0 + lr;

        float a0 = 0.f, a1 = 0.f, a2 = 0.f, a3 = 0.f;
        if (r < E) {
            const int start = g_offsets[r];
            const int cnt   = g_counts[r];
            int i = 0;
            for (; i + 8 <= cnt; i += 8) {
                int s[8];
                #pragma unroll
                for (int j = 0; j < 8; j++)
                    s[j] = g_src_sorted[start + i + j];
                float4 v[8];
                #pragma unroll
                for (int j = 0; j < 8; j++)
                    v[j] = *reinterpret_cast<const float4*>(fb + (long)s[j] * 64);
                #pragma unroll
                for (int j = 0; j < 8; j++) {
                    a0 += v[j].x; a1 += v[j].y; a2 += v[j].z; a3 += v[j].w;
                }
            }
            for (; i < cnt; i++) {
                int s = g_src_sorted[start + i];
                float4 v = *reinterpret_cast<const float4*>(fb + (long)s * 64);
                a0 += v.x; a1 += v.y; a2 += v.z; a3 += v.w;
            }
        }
        // deposit transposed: columns k = lane16*4+j, row lr
        sA[(lane16 * 4 + 0) * 66 + lr] = a0;
        sA[(lane16 * 4 + 1) * 66 + lr] = a1;
        sA[(lane16 * 4 + 2) * 66 + lr] = a2;
        sA[(lane16 * 4 + 3) * 66 + lr] = a3;
    }
    __syncthreads();

    // ---- Phase 2: 64x64 GEMM (f32x2), bias, store ------------------------
    const int rt = tid >> 4;
    const int ct = tid & 15;

    unsigned long long accq[2][4];
    #pragma unroll
    for (int rp = 0; rp < 2; rp++)
        #pragma unroll
        for (int j = 0; j < 4; j++)
            accq[rp][j] = 0ULL;

    #pragma unroll
    for (int k = 0; k < 64; k++) {
        const unsigned long long a01 =
            *reinterpret_cast<const unsigned long long*>(&sA[k * 66 + rt * 4]);
        const unsigned long long a23 =
            *reinterpret_cast<const unsigned long long*>(&sA[k * 66 + rt * 4 + 2]);
        const float4 w = *reinterpret_cast<const float4*>(&sW[k * 64 + ct * 4]);

        unsigned long long wx, wy, wz, ww;
        PACK2(wx, w.x); PACK2(wy, w.y); PACK2(wz, w.z); PACK2(ww, w.w);

        FMA2(accq[0][0], a01, wx); FMA2(accq[0][1], a01, wy);
        FMA2(accq[0][2], a01, wz); FMA2(accq[0][3], a01, ww);
        FMA2(accq[1][0], a23, wx); FMA2(accq[1][1], a23, wy);
        FMA2(accq[1][2], a23, wz); FMA2(accq[1][3], a23, ww);
    }

    float res[4][4];
    #pragma unroll
    for (int rp = 0; rp < 2; rp++)
        #pragma unroll
        for (int j = 0; j < 4; j++) {
            float lo, hi;
            UNPACK2(lo, hi, accq[rp][j]);
            res[rp * 2 + 0][j] = lo;
            res[rp * 2 + 1][j] = hi;
        }

    const float4 b = *reinterpret_cast<const float4*>(&bias[ct * 4]);

    #pragma unroll
    for (int i = 0; i < 4; i++) {
        int row = row0 + rt * 4 + i;
        if (row < E) {
            float4 v;
            v.x = res[i][0] + b.x;
            v.y = res[i][1] + b.y;
            v.z = res[i][2] + b.z;
            v.w = res[i][3] + b.w;
            *reinterpret_cast<float4*>(&out[row * 64 + ct * 4]) = v;
        }
    }
}

// ---------------------------------------------------------------------------
extern "C" void kernel_launch(void* const* d_in, const int* in_sizes, int n_in,
                              void* d_out, int out_size)
{
    const float* feat = (const float*)d_in[0];   // [E, 64] f32
    const int*   nbr  = (const int*)d_in[1];     // [P, 2]  i32
    const float* W    = (const float*)d_in[2];   // [64, 64] f32
    const float* bias = (const float*)d_in[3];   // [64] f32
    float* out = (float*)d_out;                  // [E, 64] f32

    const int E = in_sizes[0] / 64;
    const int P = in_sizes[1] / 2;

    const int blkE  = (E + 255) / 256;
    const int P2    = (P + 1) / 2;
    const int blkP2 = (P2 + 255) / 256;
    const int NB    = (E + 1023) / 1024;         // <= 512

    zero_counts_kernel<<<blkE, 256>>>(E);
    hist_kernel<<<blkP2, 256>>>((const int4*)nbr, P2, P);
    scan_partial_kernel<<<NB, 256>>>(E);
    scan_blocksums_kernel<<<1, 512>>>(NB);
    scan_final_kernel<<<NB, 256>>>(E);
    sort_scatter_kernel<<<blkP2, 256>>>((const int4*)nbr, P2, P);

    const int blkA = (E + 63) / 64;
    agg_gemm_kernel<<<blkA, 256>>>(feat, W, bias, out, E);
}